// round 3
// baseline (speedup 1.0000x reference)
#include <cuda_runtime.h>

// Tensor: (1024, 1024, 3, 3) fp32
#define OC_N    1024
#define IC_N    1024
#define ROWS_N  (OC_N * IC_N)        // 1048576 kernel rows of 9
#define N_TOT   (ROWS_N * 9)         // 9437184
#define N_VEC4  (N_TOT / 4)          // 2359296
#define MAX_GRID 1152                // 1152*256 threads * 8 float4 = N_VEC4 exactly

__device__ float              g_part_max[MAX_GRID];
__device__ float              g_scale;
__device__ float              g_rcp;
__device__ float              g_part_resid[ROWS_N / 256]; // 4096 block partials
__device__ unsigned long long g_row_cand[ROWS_N];         // 8 MB (L2-resident)

// ---------------------------------------------------------------------------
// Pass A: per-block max|t| partials (no atomics, no init kernel needed).
__global__ void __launch_bounds__(256) k_maxabs(const float4* __restrict__ in) {
    const int base = blockIdx.x * 256 + threadIdx.x;
    const int stride = MAX_GRID * 256;
    float m = 0.0f;
#pragma unroll
    for (int k = 0; k < 8; k++) {
        float4 v = in[base + k * stride];
        m = fmaxf(m, fmaxf(fmaxf(fabsf(v.x), fabsf(v.y)),
                           fmaxf(fabsf(v.z), fabsf(v.w))));
    }
#pragma unroll
    for (int o = 16; o > 0; o >>= 1)
        m = fmaxf(m, __shfl_xor_sync(0xFFFFFFFFu, m, o));
    __shared__ float sm[8];
    if ((threadIdx.x & 31) == 0) sm[threadIdx.x >> 5] = m;
    __syncthreads();
    if (threadIdx.x == 0) {
        m = sm[0];
#pragma unroll
        for (int i = 1; i < 8; i++) m = fmaxf(m, sm[i]);
        g_part_max[blockIdx.x] = m;
    }
}

// ---------------------------------------------------------------------------
// Final max reduce + scale = max/127 (IEEE) + correctly-rounded reciprocal.
__global__ void __launch_bounds__(128) k_prep() {
    float m = 0.0f;
    for (int i = threadIdx.x; i < MAX_GRID; i += 128)
        m = fmaxf(m, g_part_max[i]);
#pragma unroll
    for (int o = 16; o > 0; o >>= 1)
        m = fmaxf(m, __shfl_xor_sync(0xFFFFFFFFu, m, o));
    __shared__ float sm[4];
    if ((threadIdx.x & 31) == 0) sm[threadIdx.x >> 5] = m;
    __syncthreads();
    if (threadIdx.x == 0) {
        m = fmaxf(fmaxf(sm[0], sm[1]), fmaxf(sm[2], sm[3]));
        float s = __fdiv_rn(m, 127.0f);
        g_scale  = s;
        g_rcp    = __frcp_rn(s);
    }
}

// ---------------------------------------------------------------------------
// Pass B: per kernel-row (9 elems) SQuant stage.
__global__ void __launch_bounds__(256) k_rows(const float* __restrict__ in,
                                              float* __restrict__ out) {
    __shared__ __align__(16) float tile[2304];  // 9216 B
    __shared__ float swred[8];

    const float4* in4 = reinterpret_cast<const float4*>(in)
                        + (size_t)blockIdx.x * 576;
    float4* t4 = reinterpret_cast<float4*>(tile);
#pragma unroll
    for (int i = threadIdx.x; i < 576; i += 256) t4[i] = in4[i];
    __syncthreads();

    const float scl = g_scale;
    const float rcp = g_rcp;

    // gcd(9,32)=1 -> thread*9+i is bank-conflict-free across a warp.
    float rn[9], re[9], p[9];
    float esum = 0.0f;
#pragma unroll
    for (int i = 0; i < 9; i++) {
        float t  = tile[threadIdx.x * 9 + i];
        float q0 = __fmul_rn(t, rcp);                          // Markstein div:
        float x  = __fmaf_rn(__fmaf_rn(-scl, q0, t), rcp, q0); // == t/scl (RN)
        x = fminf(fmaxf(x, -127.0f), 127.0f);
        float r = rintf(x);           // round-half-to-even == jnp.round
        rn[i] = r;
        re[i] = __fadd_rn(r, -x);
        esum  = __fadd_rn(esum, re[i]);
    }

    const int   nf = (int)rintf(fabsf(esum));
    const bool  up = (esum < 0.0f);
    const float d1 = up ? 1.0f : -1.0f;
#pragma unroll
    for (int i = 0; i < 9; i++) {
        float c = up ? -re[i] : re[i];   // candidate iff re has right sign
        p[i] = fmaxf(c, 0.0f);
    }

    // Pairwise stable rank: tie (==) -> lower index outranks.
    int rank[9];
#pragma unroll
    for (int j = 0; j < 9; j++) rank[j] = j;
#pragma unroll
    for (int i = 0; i < 8; i++)
#pragma unroll
        for (int j = i + 1; j < 9; j++) {
            int g = (int)(p[j] > p[i]);
            rank[i] += g;
            rank[j] -= g;
        }

    // Flips: exactly nf flipped (nf <= #candidates holds in stage 1).
    int bi = -1;
#pragma unroll
    for (int i = 0; i < 9; i++) {
        if (rank[i] < nf)      rn[i] += d1;
        if (rank[i] == nf - 1) bi = i;          // boundary element
        tile[threadIdx.x * 9 + i] = rn[i];      // own slots only: no hazard
    }
    float resid = __fmaf_rn((float)nf, d1, esum);

    unsigned long long cand = 0ull;
    const int row = blockIdx.x * 256 + threadIdx.x;
    if (bi >= 0) {
        float re2 = __fadd_rn(re[bi], d1);
        int elemFlat = (row & (IC_N - 1)) * 9 + bi;
        cand = ((unsigned long long)(up ? 1u : 0u) << 63)
             | ((unsigned long long)__float_as_uint(fabsf(re2)) << 32)
             | (unsigned long long)(unsigned)(9216 - elemFlat);
    }
    g_row_cand[row] = cand;

    // block-reduce residual -> one partial per 256 rows
#pragma unroll
    for (int o = 16; o > 0; o >>= 1)
        resid += __shfl_xor_sync(0xFFFFFFFFu, resid, o);
    if ((threadIdx.x & 31) == 0) swred[threadIdx.x >> 5] = resid;
    __syncthreads();
    if (threadIdx.x == 0) {
        float s = swred[0];
#pragma unroll
        for (int i = 1; i < 8; i++) s += swred[i];
        g_part_resid[blockIdx.x] = s;
    }

    float4* out4 = reinterpret_cast<float4*>(out) + (size_t)blockIdx.x * 576;
#pragma unroll
    for (int i = threadIdx.x; i < 576; i += 256) {
        float4 v = t4[i];
        v.x = __fmul_rn(v.x, scl); v.y = __fmul_rn(v.y, scl);
        v.z = __fmul_rn(v.z, scl); v.w = __fmul_rn(v.w, scl);
        out4[i] = v;
    }
}

// ---------------------------------------------------------------------------
// Pass C: one WARP per OC channel. All 1024 candidate keys live in registers
// (32 x u64 per lane). Top-nf extraction: per pick, one 5-step xor-shfl
// 64-bit max; then every lane rebuilds its local max over keys strictly
// below the winner (keys are unique -> "< winner" excludes exactly the
// already-picked set; picks descend monotonically). No smem, no syncwarp.
__global__ void __launch_bounds__(256) k_channel(float* __restrict__ out) {
    const int oc   = (blockIdx.x << 3) | (threadIdx.x >> 5);
    const int lane = threadIdx.x & 31;

    // esum for this oc (4 block partials, fixed order; redundant per lane)
    const int pb = oc << 2;
    const float esum = ((g_part_resid[pb] + g_part_resid[pb + 1])
                      + g_part_resid[pb + 2]) + g_part_resid[pb + 3];
    const int nf = (int)rintf(fabsf(esum));
    if (nf == 0) return;
    const bool upc = (esum < 0.0f);
    // stage-2 up-flip reverts a stage-1 DOWN-flipped boundary (dir bit 0)
    const unsigned long long want  = upc ? 0ull : 1ull;
    const float              delta = upc ? g_scale : -g_scale;

    // Load & filter 1024 keys: lane holds keys j*32+lane, j=0..31 (coalesced)
    unsigned long long key[32];
    const size_t base = (size_t)oc << 10;
#pragma unroll
    for (int j = 0; j < 32; j++) {
        unsigned long long k = g_row_cand[base + j * 32 + lane];
        key[j] = (k != 0ull && (k >> 63) == want)
                     ? (k & 0x7FFFFFFFFFFFFFFFull) : 0ull;
    }

    // initial per-lane max (register tree)
    unsigned long long lmax = 0ull;
#pragma unroll
    for (int j = 0; j < 32; j++) lmax = (key[j] > lmax) ? key[j] : lmax;

    float* const ochan = out + (size_t)oc * 9216;
    for (int it = 0; it < nf; it++) {
        unsigned long long m = lmax;
#pragma unroll
        for (int o = 16; o > 0; o >>= 1) {
            unsigned long long v = __shfl_xor_sync(0xFFFFFFFFu, m, o);
            m = (v > m) ? v : m;
        }
        if (m == 0ull) break;       // candidates exhausted (safe clamp)
        if (lane == 0) {
            const int elemFlat = 9216 - (int)(unsigned)(m & 0xFFFFFFFFull);
            ochan[elemFlat] += delta;   // revert that row's stage-1 flip
        }
        // rebuild local max over keys strictly below the winner
        unsigned long long nm = 0ull;
#pragma unroll
        for (int j = 0; j < 32; j++) {
            unsigned long long k = (key[j] < m) ? key[j] : 0ull;
            nm = (k > nm) ? k : nm;
        }
        lmax = nm;
    }
}

// ---------------------------------------------------------------------------
extern "C" void kernel_launch(void* const* d_in, const int* in_sizes, int n_in,
                              void* d_out, int out_size) {
    const float* in  = (const float*)d_in[0];
    float*       out = (float*)d_out;

    k_maxabs<<<MAX_GRID, 256>>>((const float4*)in);
    k_prep<<<1, 128>>>();
    k_rows<<<ROWS_N / 256, 256>>>(in, out);
    k_channel<<<OC_N / 8, 256>>>(out);
}

// round 4
// speedup vs baseline: 1.1755x; 1.1755x over previous
#include <cuda_runtime.h>

// Tensor: (1024, 1024, 3, 3) fp32
#define OC_N    1024
#define IC_N    1024
#define ROWS_N  (OC_N * IC_N)        // 1048576 kernel rows of 9
#define N_TOT   (ROWS_N * 9)         // 9437184
#define N_VEC4  (N_TOT / 4)          // 2359296
#define MAX_GRID 1152                // 1152*256 threads * 8 float4 = N_VEC4 exactly

__device__ float    g_part_max[MAX_GRID];
__device__ float    g_scale;
__device__ float    g_rcp;
__device__ float    g_part_resid[ROWS_N / 256];   // 4096 block partials
__device__ unsigned g_row_cand[ROWS_N];           // 4 MB, 32-bit keys

// ---------------------------------------------------------------------------
// Pass A: per-block max|t| partials (no atomics, no init kernel needed).
__global__ void __launch_bounds__(256) k_maxabs(const float4* __restrict__ in) {
    const int base = blockIdx.x * 256 + threadIdx.x;
    const int stride = MAX_GRID * 256;
    float m = 0.0f;
#pragma unroll
    for (int k = 0; k < 8; k++) {
        float4 v = in[base + k * stride];
        m = fmaxf(m, fmaxf(fmaxf(fabsf(v.x), fabsf(v.y)),
                           fmaxf(fabsf(v.z), fabsf(v.w))));
    }
#pragma unroll
    for (int o = 16; o > 0; o >>= 1)
        m = fmaxf(m, __shfl_xor_sync(0xFFFFFFFFu, m, o));
    __shared__ float sm[8];
    if ((threadIdx.x & 31) == 0) sm[threadIdx.x >> 5] = m;
    __syncthreads();
    if (threadIdx.x == 0) {
        m = sm[0];
#pragma unroll
        for (int i = 1; i < 8; i++) m = fmaxf(m, sm[i]);
        g_part_max[blockIdx.x] = m;
    }
}

// ---------------------------------------------------------------------------
// Final max reduce + scale = max/127 (IEEE) + correctly-rounded reciprocal.
__global__ void __launch_bounds__(128) k_prep() {
    float m = 0.0f;
    for (int i = threadIdx.x; i < MAX_GRID; i += 128)
        m = fmaxf(m, g_part_max[i]);
#pragma unroll
    for (int o = 16; o > 0; o >>= 1)
        m = fmaxf(m, __shfl_xor_sync(0xFFFFFFFFu, m, o));
    __shared__ float sm[4];
    if ((threadIdx.x & 31) == 0) sm[threadIdx.x >> 5] = m;
    __syncthreads();
    if (threadIdx.x == 0) {
        m = fmaxf(fmaxf(sm[0], sm[1]), fmaxf(sm[2], sm[3]));
        float s = __fdiv_rn(m, 127.0f);
        g_scale  = s;
        g_rcp    = __frcp_rn(s);
    }
}

// ---------------------------------------------------------------------------
// Pass B: per kernel-row (9 elems) SQuant stage.
__global__ void __launch_bounds__(256) k_rows(const float* __restrict__ in,
                                              float* __restrict__ out) {
    __shared__ __align__(16) float tile[2304];  // 9216 B
    __shared__ float swred[8];

    const float4* in4 = reinterpret_cast<const float4*>(in)
                        + (size_t)blockIdx.x * 576;
    float4* t4 = reinterpret_cast<float4*>(tile);
#pragma unroll
    for (int i = threadIdx.x; i < 576; i += 256) t4[i] = in4[i];
    __syncthreads();

    const float scl = g_scale;
    const float rcp = g_rcp;

    // gcd(9,32)=1 -> thread*9+i is bank-conflict-free across a warp.
    float rn[9], re[9], p[9];
    float esum = 0.0f;
#pragma unroll
    for (int i = 0; i < 9; i++) {
        float t  = tile[threadIdx.x * 9 + i];
        float q0 = __fmul_rn(t, rcp);                          // Markstein div:
        float x  = __fmaf_rn(__fmaf_rn(-scl, q0, t), rcp, q0); // == t/scl (RN)
        x = fminf(fmaxf(x, -127.0f), 127.0f);
        float r = rintf(x);           // round-half-to-even == jnp.round
        rn[i] = r;
        re[i] = __fadd_rn(r, -x);
        esum  = __fadd_rn(esum, re[i]);
    }

    const int   nf = (int)rintf(fabsf(esum));
    const bool  up = (esum < 0.0f);
    const float d1 = up ? 1.0f : -1.0f;
#pragma unroll
    for (int i = 0; i < 9; i++) {
        float c = up ? -re[i] : re[i];   // candidate iff re has right sign
        p[i] = fmaxf(c, 0.0f);
    }

    // Pairwise stable rank: tie (==) -> lower index outranks.
    int rank[9];
#pragma unroll
    for (int j = 0; j < 9; j++) rank[j] = j;
#pragma unroll
    for (int i = 0; i < 8; i++)
#pragma unroll
        for (int j = i + 1; j < 9; j++) {
            int g = (int)(p[j] > p[i]);
            rank[i] += g;
            rank[j] -= g;
        }

    // Flips: exactly nf flipped (nf <= #candidates holds in stage 1).
    int bi = -1;
#pragma unroll
    for (int i = 0; i < 9; i++) {
        if (rank[i] < nf)      rn[i] += d1;
        if (rank[i] == nf - 1) bi = i;          // boundary element
        tile[threadIdx.x * 9 + i] = rn[i];      // own slots only: no hazard
    }
    float resid = __fmaf_rn((float)nf, d1, esum);

    // 32-bit candidate key: dir(1) | prio17 | (9216-idx)(14).
    // |re2| in [0.5, 1) -> exponent fixed at 126; mantissa alone orders it.
    unsigned cand = 0u;
    const int row = blockIdx.x * 256 + threadIdx.x;
    if (bi >= 0) {
        float re2 = __fadd_rn(re[bi], d1);
        int elemFlat = (row & (IC_N - 1)) * 9 + bi;
        unsigned mant = __float_as_uint(fabsf(re2)) & 0x7FFFFFu;
        cand = ((up ? 1u : 0u) << 31) | ((mant >> 6) << 14)
             | (unsigned)(9216 - elemFlat);
    }
    g_row_cand[row] = cand;

    // block-reduce residual -> one partial per 256 rows
#pragma unroll
    for (int o = 16; o > 0; o >>= 1)
        resid += __shfl_xor_sync(0xFFFFFFFFu, resid, o);
    if ((threadIdx.x & 31) == 0) swred[threadIdx.x >> 5] = resid;
    __syncthreads();
    if (threadIdx.x == 0) {
        float s = swred[0];
#pragma unroll
        for (int i = 1; i < 8; i++) s += swred[i];
        g_part_resid[blockIdx.x] = s;
    }

    float4* out4 = reinterpret_cast<float4*>(out) + (size_t)blockIdx.x * 576;
#pragma unroll
    for (int i = threadIdx.x; i < 576; i += 256) {
        float4 v = t4[i];
        v.x = __fmul_rn(v.x, scl); v.y = __fmul_rn(v.y, scl);
        v.z = __fmul_rn(v.z, scl); v.w = __fmul_rn(v.w, scl);
        out4[i] = v;
    }
}

// ---------------------------------------------------------------------------
// Pass C: one WARP per OC channel, 1024 u32 keys in registers (32/lane, no
// spill). Per pick: REDUX.UMAX warp max, owner patches out, then a 5-level
// register IMNMX tree rebuilds the per-lane max over keys strictly below the
// winner (keys unique -> "< winner" excludes exactly the picked set).
__global__ void __launch_bounds__(256) k_channel(float* __restrict__ out) {
    const int oc   = (blockIdx.x << 3) | (threadIdx.x >> 5);
    const int lane = threadIdx.x & 31;

    const int pb = oc << 2;
    const float esum = ((g_part_resid[pb] + g_part_resid[pb + 1])
                      + g_part_resid[pb + 2]) + g_part_resid[pb + 3];
    const int nf = (int)rintf(fabsf(esum));
    if (nf == 0) return;
    const bool upc = (esum < 0.0f);
    // stage-2 up-flip reverts a stage-1 DOWN-flipped boundary (dir bit 0)
    const unsigned want  = upc ? 0u : 1u;
    const float    delta = upc ? g_scale : -g_scale;

    // Load 1024 keys as uint4 (coalesced 512B/instr), filter by direction.
    const uint4* p = reinterpret_cast<const uint4*>(g_row_cand)
                     + ((size_t)oc << 8);
    unsigned key[32];
#pragma unroll
    for (int j = 0; j < 8; j++) {
        uint4 v = p[j * 32 + lane];
        key[j*4+0] = (v.x != 0u && (v.x >> 31) == want) ? (v.x & 0x7FFFFFFFu) : 0u;
        key[j*4+1] = (v.y != 0u && (v.y >> 31) == want) ? (v.y & 0x7FFFFFFFu) : 0u;
        key[j*4+2] = (v.z != 0u && (v.z >> 31) == want) ? (v.z & 0x7FFFFFFFu) : 0u;
        key[j*4+3] = (v.w != 0u && (v.w >> 31) == want) ? (v.w & 0x7FFFFFFFu) : 0u;
    }

    // per-lane max, explicit tree for ILP
    unsigned lmax;
    {
        unsigned t[32];
#pragma unroll
        for (int j = 0; j < 32; j++) t[j] = key[j];
#pragma unroll
        for (int s = 16; s > 0; s >>= 1)
#pragma unroll
            for (int j = 0; j < 16; j++)
                if (j < s) t[j] = umax(t[j], t[j + s]);
        lmax = t[0];
    }

    float* const ochan = out + (size_t)oc * 9216;
    for (int it = 0; it < nf; it++) {
        const unsigned m = __reduce_max_sync(0xFFFFFFFFu, lmax);
        if (m == 0u) break;                 // candidates exhausted (safe clamp)
        if (lmax == m) {                    // unique owner (keys unique)
            const int elemFlat = 9216 - (int)(m & 0x3FFFu);
            ochan[elemFlat] += delta;       // revert that row's stage-1 flip
        }
        // rebuild per-lane max over keys strictly below the winner
        unsigned t[32];
#pragma unroll
        for (int j = 0; j < 32; j++) t[j] = (key[j] < m) ? key[j] : 0u;
#pragma unroll
        for (int s = 16; s > 0; s >>= 1)
#pragma unroll
            for (int j = 0; j < 16; j++)
                if (j < s) t[j] = umax(t[j], t[j + s]);
        lmax = t[0];
    }
}

// ---------------------------------------------------------------------------
extern "C" void kernel_launch(void* const* d_in, const int* in_sizes, int n_in,
                              void* d_out, int out_size) {
    const float* in  = (const float*)d_in[0];
    float*       out = (float*)d_out;

    k_maxabs<<<MAX_GRID, 256>>>((const float4*)in);
    k_prep<<<1, 128>>>();
    k_rows<<<ROWS_N / 256, 256>>>(in, out);
    k_channel<<<OC_N / 8, 256>>>(out);
}

// round 5
// speedup vs baseline: 1.3107x; 1.1150x over previous
#include <cuda_runtime.h>

// Tensor: (1024, 1024, 3, 3) fp32
#define OC_N    1024
#define IC_N    1024
#define ROWS_N  (OC_N * IC_N)        // 1048576 kernel rows of 9
#define N_TOT   (ROWS_N * 9)         // 9437184
#define N_VEC4  (N_TOT / 4)          // 2359296
#define MAX_GRID 1152                // 1152*256 threads * 8 float4 = N_VEC4 exactly

__device__ float    g_part_max[MAX_GRID];
__device__ float    g_scale;
__device__ float    g_rcp;
__device__ float    g_part_resid[ROWS_N / 256];   // 4096 block partials
__device__ unsigned g_row_cand[ROWS_N];           // 4 MB, 32-bit keys

// ---------------------------------------------------------------------------
// Pass A: per-block max|t| partials (no atomics, no init kernel needed).
__global__ void __launch_bounds__(256) k_maxabs(const float4* __restrict__ in) {
    const int base = blockIdx.x * 256 + threadIdx.x;
    const int stride = MAX_GRID * 256;
    float m = 0.0f;
#pragma unroll
    for (int k = 0; k < 8; k++) {
        float4 v = in[base + k * stride];
        m = fmaxf(m, fmaxf(fmaxf(fabsf(v.x), fabsf(v.y)),
                           fmaxf(fabsf(v.z), fabsf(v.w))));
    }
#pragma unroll
    for (int o = 16; o > 0; o >>= 1)
        m = fmaxf(m, __shfl_xor_sync(0xFFFFFFFFu, m, o));
    __shared__ float sm[8];
    if ((threadIdx.x & 31) == 0) sm[threadIdx.x >> 5] = m;
    __syncthreads();
    if (threadIdx.x == 0) {
        m = sm[0];
#pragma unroll
        for (int i = 1; i < 8; i++) m = fmaxf(m, sm[i]);
        g_part_max[blockIdx.x] = m;
    }
}

// ---------------------------------------------------------------------------
// Final max reduce + scale = max/127 (IEEE) + correctly-rounded reciprocal.
__global__ void __launch_bounds__(128) k_prep() {
    float m = 0.0f;
    for (int i = threadIdx.x; i < MAX_GRID; i += 128)
        m = fmaxf(m, g_part_max[i]);
#pragma unroll
    for (int o = 16; o > 0; o >>= 1)
        m = fmaxf(m, __shfl_xor_sync(0xFFFFFFFFu, m, o));
    __shared__ float sm[4];
    if ((threadIdx.x & 31) == 0) sm[threadIdx.x >> 5] = m;
    __syncthreads();
    if (threadIdx.x == 0) {
        m = fmaxf(fmaxf(sm[0], sm[1]), fmaxf(sm[2], sm[3]));
        float s = __fdiv_rn(m, 127.0f);
        g_scale  = s;
        g_rcp    = __frcp_rn(s);
    }
}

// ---------------------------------------------------------------------------
// Pass B: per kernel-row (9 elems) SQuant stage.
__global__ void __launch_bounds__(256) k_rows(const float* __restrict__ in,
                                              float* __restrict__ out) {
    __shared__ __align__(16) float tile[2304];  // 9216 B
    __shared__ float swred[8];

    const float4* in4 = reinterpret_cast<const float4*>(in)
                        + (size_t)blockIdx.x * 576;
    float4* t4 = reinterpret_cast<float4*>(tile);
#pragma unroll
    for (int i = threadIdx.x; i < 576; i += 256) t4[i] = in4[i];
    __syncthreads();

    const float scl = g_scale;
    const float rcp = g_rcp;

    // gcd(9,32)=1 -> thread*9+i is bank-conflict-free across a warp.
    float rn[9], re[9], p[9];
    float esum = 0.0f;
#pragma unroll
    for (int i = 0; i < 9; i++) {
        float t  = tile[threadIdx.x * 9 + i];
        float q0 = __fmul_rn(t, rcp);                          // Markstein div:
        float x  = __fmaf_rn(__fmaf_rn(-scl, q0, t), rcp, q0); // == t/scl (RN)
        x = fminf(fmaxf(x, -127.0f), 127.0f);
        float r = rintf(x);           // round-half-to-even == jnp.round
        rn[i] = r;
        re[i] = __fadd_rn(r, -x);
        esum  = __fadd_rn(esum, re[i]);
    }

    const int   nf = (int)rintf(fabsf(esum));
    const bool  up = (esum < 0.0f);
    const float d1 = up ? 1.0f : -1.0f;
#pragma unroll
    for (int i = 0; i < 9; i++) {
        float c = up ? -re[i] : re[i];   // candidate iff re has right sign
        p[i] = fmaxf(c, 0.0f);
    }

    // Pairwise stable rank: tie (==) -> lower index outranks.
    int rank[9];
#pragma unroll
    for (int j = 0; j < 9; j++) rank[j] = j;
#pragma unroll
    for (int i = 0; i < 8; i++)
#pragma unroll
        for (int j = i + 1; j < 9; j++) {
            int g = (int)(p[j] > p[i]);
            rank[i] += g;
            rank[j] -= g;
        }

    // Flips: exactly nf flipped (nf <= #candidates holds in stage 1).
    int bi = -1;
#pragma unroll
    for (int i = 0; i < 9; i++) {
        if (rank[i] < nf)      rn[i] += d1;
        if (rank[i] == nf - 1) bi = i;          // boundary element
        tile[threadIdx.x * 9 + i] = rn[i];      // own slots only: no hazard
    }
    float resid = __fmaf_rn((float)nf, d1, esum);

    // 32-bit candidate key: dir(1) | prio17 | (9216-idx)(14).
    // |re2| in [0.5, 1) -> exponent fixed at 126; mantissa alone orders it.
    unsigned cand = 0u;
    const int row = blockIdx.x * 256 + threadIdx.x;
    if (bi >= 0) {
        float re2 = __fadd_rn(re[bi], d1);
        int elemFlat = (row & (IC_N - 1)) * 9 + bi;
        unsigned mant = __float_as_uint(fabsf(re2)) & 0x7FFFFFu;
        cand = ((up ? 1u : 0u) << 31) | ((mant >> 6) << 14)
             | (unsigned)(9216 - elemFlat);
    }
    g_row_cand[row] = cand;

    // block-reduce residual -> one partial per 256 rows
#pragma unroll
    for (int o = 16; o > 0; o >>= 1)
        resid += __shfl_xor_sync(0xFFFFFFFFu, resid, o);
    if ((threadIdx.x & 31) == 0) swred[threadIdx.x >> 5] = resid;
    __syncthreads();
    if (threadIdx.x == 0) {
        float s = swred[0];
#pragma unroll
        for (int i = 1; i < 8; i++) s += swred[i];
        g_part_resid[blockIdx.x] = s;
    }

    float4* out4 = reinterpret_cast<float4*>(out) + (size_t)blockIdx.x * 576;
#pragma unroll
    for (int i = threadIdx.x; i < 576; i += 256) {
        float4 v = t4[i];
        v.x = __fmul_rn(v.x, scl); v.y = __fmul_rn(v.y, scl);
        v.z = __fmul_rn(v.z, scl); v.w = __fmul_rn(v.w, scl);
        out4[i] = v;
    }
}

// ---------------------------------------------------------------------------
// Pass C: one WARP per OC channel, 1024 u32 keys in registers (32/lane).
// The pick loop touches NO global memory: per pick, REDUX.UMAX warp max,
// lane 0 records the pick into a per-warp smem list (STS = issue-only, never
// stalls), then a register select+umax tree rebuilds the per-lane max over
// keys strictly below the winner (keys unique -> "< winner" excludes exactly
// the picked set). All global RMW patches are applied AFTER the loop by all
// 32 lanes in parallel (distinct addresses, MLP = npick: one latency total).
__global__ void __launch_bounds__(256) k_channel(float* __restrict__ out) {
    __shared__ unsigned spatch[8][512];      // per-warp pick list (nf <= 512)

    const int wslot = threadIdx.x >> 5;
    const int oc    = (blockIdx.x << 3) | wslot;
    const int lane  = threadIdx.x & 31;

    const int pb = oc << 2;
    const float esum = ((g_part_resid[pb] + g_part_resid[pb + 1])
                      + g_part_resid[pb + 2]) + g_part_resid[pb + 3];
    const int nf = (int)rintf(fabsf(esum));
    if (nf == 0) return;
    const bool upc = (esum < 0.0f);
    // stage-2 up-flip reverts a stage-1 DOWN-flipped boundary (dir bit 0)
    const unsigned want  = upc ? 0u : 1u;
    const float    delta = upc ? g_scale : -g_scale;

    // Load 1024 keys as uint4 (coalesced 512B/instr), filter by direction.
    const uint4* p = reinterpret_cast<const uint4*>(g_row_cand)
                     + ((size_t)oc << 8);
    unsigned key[32];
#pragma unroll
    for (int j = 0; j < 8; j++) {
        uint4 v = p[j * 32 + lane];
        key[j*4+0] = (v.x != 0u && (v.x >> 31) == want) ? (v.x & 0x7FFFFFFFu) : 0u;
        key[j*4+1] = (v.y != 0u && (v.y >> 31) == want) ? (v.y & 0x7FFFFFFFu) : 0u;
        key[j*4+2] = (v.z != 0u && (v.z >> 31) == want) ? (v.z & 0x7FFFFFFFu) : 0u;
        key[j*4+3] = (v.w != 0u && (v.w >> 31) == want) ? (v.w & 0x7FFFFFFFu) : 0u;
    }

    // per-lane max, explicit tree for ILP
    unsigned lmax;
    {
        unsigned t[32];
#pragma unroll
        for (int j = 0; j < 32; j++) t[j] = key[j];
#pragma unroll
        for (int s = 16; s > 0; s >>= 1)
#pragma unroll
            for (int j = 0; j < 16; j++)
                if (j < s) t[j] = umax(t[j], t[j + s]);
        lmax = t[0];
    }

    unsigned* const patch = spatch[wslot];
    int npick = 0;
    for (int it = 0; it < nf; it++) {
        const unsigned m = __reduce_max_sync(0xFFFFFFFFu, lmax);
        if (m == 0u) break;                 // candidates exhausted (safe clamp)
        if (lane == 0) patch[npick] = m;    // STS only: off the critical path
        npick++;
        // rebuild per-lane max over keys strictly below the winner
        unsigned t[32];
#pragma unroll
        for (int j = 0; j < 32; j++) t[j] = (key[j] < m) ? key[j] : 0u;
#pragma unroll
        for (int s = 16; s > 0; s >>= 1)
#pragma unroll
            for (int j = 0; j < 16; j++)
                if (j < s) t[j] = umax(t[j], t[j + s]);
        lmax = t[0];
    }
    __syncwarp();

    // Apply all patches in parallel: distinct elements, latencies overlap.
    float* const ochan = out + (size_t)oc * 9216;
    for (int i = lane; i < npick; i += 32) {
        const int elemFlat = 9216 - (int)(patch[i] & 0x3FFFu);
        ochan[elemFlat] += delta;           // revert that row's stage-1 flip
    }
}

// ---------------------------------------------------------------------------
extern "C" void kernel_launch(void* const* d_in, const int* in_sizes, int n_in,
                              void* d_out, int out_size) {
    const float* in  = (const float*)d_in[0];
    float*       out = (float*)d_out;

    k_maxabs<<<MAX_GRID, 256>>>((const float4*)in);
    k_prep<<<1, 128>>>();
    k_rows<<<ROWS_N / 256, 256>>>(in, out);
    k_channel<<<OC_N / 8, 256>>>(out);
}